// round 15
// baseline (speedup 1.0000x reference)
#include <cuda_runtime.h>
#include <cuda_bf16.h>
#include <math_constants.h>

#define E  512
#define L  1024
#define B2 512
#define CHUNK 128
#define NPART 16     // row-group partial count; scores folds these
#define NPREP 64     // first 64 linear CTAs compute the partials

__device__ float g_scores[B2 * L];       // raw attention energies
__device__ float g_partial[NPART * E];   // prep partials (folded by all CTAs)
__device__ unsigned int g_flag;          // monotonic readiness counter

// ---------------------------------------------------------------------------
// Scores (+ embedded prep): grid (L/CHUNK, B2), 256 threads.
// CTAs linid<NPREP: compute g_partial[j] slice (j=linid>>2, cg=linid&3),
// fence, bump g_flag. All CTAs acquire-poll g_flag>=NPREP, fold partials
// into s_v, then run the R2-proven hot loop (DO NOT modify).
// Bias term dropped (softmax shift-invariance).
// ---------------------------------------------------------------------------
__global__ __launch_bounds__(256)
void scores_kernel(const float* __restrict__ q,
                   const float* __restrict__ W,
                   const float* __restrict__ wv,
                   const int*   __restrict__ lens) {
    __shared__ float s_v[E];
    __shared__ float s_wv[32];
    __shared__ float s_part[128];

    const int tid  = threadIdx.x;
    const int warp = tid >> 5;
    const int lane = tid & 31;
    const int b    = blockIdx.y;
    const int base = blockIdx.x * CHUNK;
    const int len  = lens[b];
    const int linid = blockIdx.y * gridDim.x + blockIdx.x;

    // ---- embedded prep (first-wave CTAs only) ----
    if (linid < NPREP) {
        const int j   = linid >> 2;         // 0..15 row group
        const int cg  = linid & 3;          // 0..3 col group
        const int col = tid & 127;
        const int g   = tid >> 7;           // 0..1
        const int e   = cg * 128 + col;
        const int f0  = j * 32 + g * 16;

        if (tid < 32) s_wv[tid] = __ldg(wv + j * 32 + tid);
        __syncthreads();

        float acc = 0.f;
        #pragma unroll
        for (int r = 0; r < 16; ++r)
            acc = fmaf(__ldg(W + (size_t)(f0 + r) * E + e), s_wv[g * 16 + r], acc);

        if (g == 1) s_part[col] = acc;
        __syncthreads();
        if (g == 0)
            g_partial[(size_t)j * E + e] = acc + s_part[col];

        __threadfence();                    // release partial stores
        __syncthreads();
        if (tid == 0) atomicAdd(&g_flag, 1u);
    }

    if (base >= len) return;                // whole chunk masked out

    // ---- wait for all partials (acquire) ----
    if (tid == 0) {
        unsigned int v;
        for (;;) {
            asm volatile("ld.acquire.gpu.global.u32 %0, [%1];"
                         : "=r"(v) : "l"(&g_flag) : "memory");
            if (v >= NPREP) break;
            __nanosleep(64);
        }
    }
    __syncthreads();

    // ---- fold partials into s_v ----
    #pragma unroll
    for (int i = tid; i < E; i += 256) {
        float s = 0.f;
        #pragma unroll
        for (int jj = 0; jj < NPART; ++jj)
            s += g_partial[jj * E + i];
        s_v[i] = s;
    }
    __syncthreads();

    const float4* __restrict__ vv = reinterpret_cast<const float4*>(s_v);
    const float*  __restrict__ qrow = q + (size_t)b * L * E;
    const int tok_end = min(base + CHUNK, len);

    for (int l = base + warp * 16; l < min(base + warp * 16 + 16, tok_end); ++l) {
        const float4* __restrict__ qp =
            reinterpret_cast<const float4*>(qrow + (size_t)l * E);
        float acc = 0.f;
        #pragma unroll
        for (int k = 0; k < 4; ++k) {
            float4 a = __ldg(qp + k * 32 + lane);
            float4 w = vv[k * 32 + lane];
            acc = fmaf(a.x, w.x, acc);
            acc = fmaf(a.y, w.y, acc);
            acc = fmaf(a.z, w.z, acc);
            acc = fmaf(a.w, w.w, acc);
        }
        #pragma unroll
        for (int o = 16; o; o >>= 1)
            acc += __shfl_down_sync(0xffffffffu, acc, o);
        if (lane == 0) g_scores[b * L + l] = acc;
    }
}

// ---------------------------------------------------------------------------
// Softmax over valid prefix. One 256-thread block per row, float4 I/O.
// PDL: lens prelude before gridsync.
// ---------------------------------------------------------------------------
__global__ __launch_bounds__(256)
void softmax_kernel(const int* __restrict__ lens,
                    float* __restrict__ out) {
    __shared__ float s_red[8];
    __shared__ float s_bcast;

    const int tid  = threadIdx.x;
    const int warp = tid >> 5;
    const int lane = tid & 31;
    const int b    = blockIdx.x;
    const int len  = lens[b];            // input, independent of scores
    const int i0   = tid * 4;

    cudaGridDependencySynchronize();     // wait for g_scores

    float4 sc = *reinterpret_cast<const float4*>(g_scores + b * L + i0);
    float x0 = (i0 + 0 < len) ? sc.x : -CUDART_INF_F;
    float x1 = (i0 + 1 < len) ? sc.y : -CUDART_INF_F;
    float x2 = (i0 + 2 < len) ? sc.z : -CUDART_INF_F;
    float x3 = (i0 + 3 < len) ? sc.w : -CUDART_INF_F;

    float m = fmaxf(fmaxf(x0, x1), fmaxf(x2, x3));
    #pragma unroll
    for (int o = 16; o; o >>= 1)
        m = fmaxf(m, __shfl_down_sync(0xffffffffu, m, o));
    if (lane == 0) s_red[warp] = m;
    __syncthreads();
    if (warp == 0) {
        float t = (lane < 8) ? s_red[lane] : -CUDART_INF_F;
        #pragma unroll
        for (int o = 4; o; o >>= 1)
            t = fmaxf(t, __shfl_down_sync(0xffffffffu, t, o));
        if (lane == 0) s_bcast = t;
    }
    __syncthreads();
    const float rowmax = s_bcast;

    float e0 = (i0 + 0 < len) ? __expf(x0 - rowmax) : 0.f;
    float e1 = (i0 + 1 < len) ? __expf(x1 - rowmax) : 0.f;
    float e2 = (i0 + 2 < len) ? __expf(x2 - rowmax) : 0.f;
    float e3 = (i0 + 3 < len) ? __expf(x3 - rowmax) : 0.f;

    float s = e0 + e1 + e2 + e3;
    #pragma unroll
    for (int o = 16; o; o >>= 1)
        s += __shfl_down_sync(0xffffffffu, s, o);
    __syncthreads();
    if (lane == 0) s_red[warp] = s;
    __syncthreads();
    if (warp == 0) {
        float t = (lane < 8) ? s_red[lane] : 0.f;
        #pragma unroll
        for (int o = 4; o; o >>= 1)
            t += __shfl_down_sync(0xffffffffu, t, o);
        if (lane == 0) s_bcast = t;
    }
    __syncthreads();
    const float inv = 1.f / s_bcast;

    float4 r = make_float4(e0 * inv, e1 * inv, e2 * inv, e3 * inv);
    *reinterpret_cast<float4*>(out + (size_t)b * L + i0) = r;
}

extern "C" void kernel_launch(void* const* d_in, const int* in_sizes, int n_in,
                              void* d_out, int out_size) {
    const float* questions = (const float*)d_in[0];   // [B2, L, E]
    const int*   lens      = (const int*)d_in[1];     // [B2]
    const float* W         = (const float*)d_in[2];   // [E, E]
    const float* wv        = (const float*)d_in[4];   // [E, 1]
    float* out             = (float*)d_out;           // [B2, L]

    scores_kernel<<<dim3(L / CHUNK, B2), 256>>>(questions, W, wv, lens);

    cudaLaunchAttribute attr[1];
    attr[0].id = cudaLaunchAttributeProgrammaticStreamSerialization;
    attr[0].val.programmaticStreamSerializationAllowed = 1;

    {   // softmax with PDL
        cudaLaunchConfig_t cfg = {};
        cfg.gridDim  = dim3(B2);
        cfg.blockDim = dim3(256);
        cfg.stream   = 0;
        cfg.attrs    = attr;
        cfg.numAttrs = 1;
        cudaLaunchKernelEx(&cfg, softmax_kernel, lens, out);
    }
}